// round 13
// baseline (speedup 1.0000x reference)
#include <cuda_runtime.h>
#include <cuda_fp16.h>
#include <cuda.h>
#include <cstdint>

#define NTOK 8192
#define DIN  512
#define DH   2048
#define DOUT 512
#define NE   8
#define TPE  64   // max m-tiles (128 rows) per expert

#if defined(__CUDA_ARCH__) && (__CUDA_ARCH__ >= 1000) && \
    (defined(__CUDA_ARCH_FEAT_SM103_ALL) || defined(__CUDA_ARCH_FEAT_SM100_ALL))
#define TC_OK 1
#else
#define TC_OK 0
#endif

// ---- scratch (__device__ globals: allocation-free rule) ----
__device__ int g_cnt[NE], g_off[NE], g_idx[NTOK];
__device__ __half g_x[(size_t)NTOK * DIN];               // sorted x (fp16)
__device__ __half g_h[(size_t)NTOK * DH];                // sorted h (fp16)
__device__ __half g_w1[(size_t)NE * DH * DIN];           // [e][n][k] fp16
__device__ __half g_w2[(size_t)NE * DOUT * DH];          // [e][n][k] fp16

// ================= helpers =================
__device__ __forceinline__ uint32_t smem_u32(const void* p) {
    uint32_t a;
    asm("{ .reg .u64 t; cvta.to.shared.u64 t, %1; cvt.u32.u64 %0, t; }" : "=r"(a) : "l"(p));
    return a;
}

static constexpr uint64_t DESC_BASE =
    (uint64_t(2) << 61) | (uint64_t(1) << 46) | (uint64_t(64) << 32) | (uint64_t(1) << 16);
__device__ __forceinline__ uint64_t mkdesc(uint32_t addr) {
    return DESC_BASE | ((uint64_t)(addr >> 4) & 0x3FFF);
}

__device__ __forceinline__ uint32_t pack2(__half a, __half b) {
    __half2 p = __halves2half2(a, b);
    return *reinterpret_cast<uint32_t*>(&p);
}

#if TC_OK
template<int NT>
__device__ __forceinline__ void mma_ss(uint32_t d, uint64_t a, uint64_t b, bool acc) {
    constexpr uint32_t IDESC = 0x08000010u | ((NT / 8) << 17);
    uint32_t en = acc ? 1u : 0u;
    asm volatile(
        "{\n\t.reg .pred p;\n\tsetp.ne.u32 p, %4, 0;\n\t"
        "tcgen05.mma.cta_group::1.kind::f16 [%0], %1, %2, %3, {%5,%5,%5,%5}, p;\n\t}"
        :: "r"(d), "l"(a), "l"(b), "r"(IDESC), "r"(en), "r"(0u) : "memory");
}

#define WAIT_PARITY(mbar, ph) do {                                              \
    uint32_t _m = (mbar), _p = (ph), _d;                                        \
    asm volatile("{\n\t.reg .pred p;\n\t"                                       \
        "mbarrier.try_wait.parity.acquire.cta.shared::cta.b64 p, [%1], %2;\n\t" \
        "selp.b32 %0,1,0,p;\n\t}" : "=r"(_d) : "r"(_m), "r"(_p) : "memory");    \
    if (!_d) {                                                                  \
        asm volatile("{\n\t.reg .pred P1;\n\t"                                  \
            "WL_%=:\n\t"                                                        \
            "mbarrier.try_wait.parity.acquire.cta.shared::cta.b64 P1, [%0], %1, 0x989680;\n\t" \
            "@P1 bra.uni WD_%=;\n\tbra.uni WL_%=;\n\tWD_%=:\n\t}"               \
            :: "r"(_m), "r"(_p) : "memory");                                    \
    }                                                                           \
} while (0)

#define TMA3D(smaddr, tmap, cx, cy, cz, mbar)                                      \
    asm volatile(                                                                  \
        "cp.async.bulk.tensor.3d.shared::cta.global.tile.mbarrier::complete_tx::bytes " \
        "[%0], [%1, {%2, %3, %4}], [%5];"                                          \
        :: "r"(smaddr), "l"(tmap), "r"(cx), "r"(cy), "r"(cz), "r"(mbar) : "memory")

#define LDTM_X32(r, ta)                                                          \
    asm volatile("tcgen05.ld.sync.aligned.32x32b.x32.b32 "                       \
        "{%0,%1,%2,%3,%4,%5,%6,%7,%8,%9,%10,%11,%12,%13,%14,%15,"                \
        "%16,%17,%18,%19,%20,%21,%22,%23,%24,%25,%26,%27,%28,%29,%30,%31}, [%32];" \
        : "=r"((r)[0]),"=r"((r)[1]),"=r"((r)[2]),"=r"((r)[3]),                   \
          "=r"((r)[4]),"=r"((r)[5]),"=r"((r)[6]),"=r"((r)[7]),                   \
          "=r"((r)[8]),"=r"((r)[9]),"=r"((r)[10]),"=r"((r)[11]),                 \
          "=r"((r)[12]),"=r"((r)[13]),"=r"((r)[14]),"=r"((r)[15]),               \
          "=r"((r)[16]),"=r"((r)[17]),"=r"((r)[18]),"=r"((r)[19]),               \
          "=r"((r)[20]),"=r"((r)[21]),"=r"((r)[22]),"=r"((r)[23]),               \
          "=r"((r)[24]),"=r"((r)[25]),"=r"((r)[26]),"=r"((r)[27]),               \
          "=r"((r)[28]),"=r"((r)[29]),"=r"((r)[30]),"=r"((r)[31])                \
        : "r"(ta))
#endif // TC_OK

// ================= routing: ONE kernel (single block) =================
__global__ void __launch_bounds__(1024) k_route(const int* __restrict__ g) {
    __shared__ int c[NE], pos[NE];
    int tid = threadIdx.x;
    if (tid < NE) { c[tid] = 0; }
    __syncthreads();
    #pragma unroll
    for (int i = tid; i < NTOK; i += 1024) atomicAdd(&c[g[i] & (NE - 1)], 1);
    __syncthreads();
    if (tid == 0) {
        int s = 0;
        for (int e = 0; e < NE; e++) { g_off[e] = s; g_cnt[e] = c[e]; pos[e] = s; s += c[e]; }
    }
    __syncthreads();
    #pragma unroll
    for (int i = tid; i < NTOK; i += 1024) {
        int e = g[i] & (NE - 1);
        int p = atomicAdd(&pos[e], 1);
        g_idx[p] = i;
    }
}

// ================= pre-conversion =================
__global__ void __launch_bounds__(256) k_convert_x(const float* __restrict__ x) {
    int i = blockIdx.x * blockDim.x + threadIdx.x;   // 0 .. NTOK*DIN/4-1
    int row = i >> 7;                 // DIN/4 = 128 float4 per row
    int c = (i & 127) * 4;
    int tok = g_idx[row];
    float4 v = *(const float4*)(x + (size_t)tok * DIN + c);
    *(uint2*)(g_x + (size_t)row * DIN + c) =
        make_uint2(pack2(__float2half_rn(v.x), __float2half_rn(v.y)),
                   pack2(__float2half_rn(v.z), __float2half_rn(v.w)));
}

// W [e][K][N] fp32 -> Wt [e][N][K] fp16 (SMEM 32x32 tile transpose)
__global__ void __launch_bounds__(256) k_convert_w(const float* __restrict__ W,
                                                   __half* __restrict__ Wt,
                                                   int K, int N) {
    __shared__ float t[32][33];
    int e = blockIdx.z;
    int k0 = blockIdx.y * 32, n0 = blockIdx.x * 32;
    int tx = threadIdx.x, ty = threadIdx.y;   // (32, 8)
    const float* Wb = W + (size_t)e * K * N;
    #pragma unroll
    for (int j = 0; j < 4; j++) {
        int kk = ty + j * 8;
        t[kk][tx] = Wb[(size_t)(k0 + kk) * N + n0 + tx];
    }
    __syncthreads();
    __half* Tb = Wt + ((size_t)e * N + n0) * K + k0;
    #pragma unroll
    for (int j = 0; j < 4; j++) {
        int nn = ty + j * 8;
        Tb[(size_t)nn * K + tx] = __float2half_rn(t[tx][nn]);
    }
}

// ================= tcgen05 fp16 GEMM, TMA pipeline, 2 CTAs/SM =================
// PHASE 1: h = relu(x_s @ W1t^T + b1)  K=512,  N=2048, NT=256, NS=2
// PHASE 2: out = h_s @ W2t^T + b2      K=2048, N=512,  NT=128, NS=3 (scatter)
template<int PHASE, int NT, int NS>
__global__ void __launch_bounds__(128, 2)
gemm_tc(const __grid_constant__ CUtensorMap tmA,
        const __grid_constant__ CUtensorMap tmB,
        const float* __restrict__ bias, float* __restrict__ OUT)
{
#if TC_OK
    constexpr int K = (PHASE == 1) ? DIN : DH;
    constexpr int N = (PHASE == 1) ? DH : DOUT;
    constexpr int NCHUNK = K / 64;
    constexpr uint32_t A_BYTES = 128 * 128;                     // 16 KB
    constexpr uint32_t B_BYTES = NT * 128;
    constexpr uint32_t STAGE_BYTES = A_BYTES + B_BYTES;
    constexpr uint32_t OFF_B = A_BYTES;

    const int e  = blockIdx.y / TPE;
    const int mt = blockIdx.y % TPE;
    const int cnt = g_cnt[e];
    const int m0  = mt * 128;
    if (m0 >= cnt) return;
    const int off = g_off[e];
    const int bn  = blockIdx.x * NT;

    extern __shared__ char smem[];
    const uint32_t sb = smem_u32(smem);
    // header: [0] tmem ptr; full mbars at 8+8s; empty at 32+8s; done at 56
    const int tid = threadIdx.x, wid = tid >> 5;

    if (wid == 0) {
        asm volatile("tcgen05.alloc.cta_group::1.sync.aligned.shared::cta.b32 [%0], %1;"
                     :: "r"(sb), "r"((uint32_t)NT) : "memory");
        asm volatile("tcgen05.relinquish_alloc_permit.cta_group::1.sync.aligned;");
    }
    __syncthreads();
    uint32_t tmem;
    asm volatile("ld.shared.b32 %0,[%1];" : "=r"(tmem) : "r"(sb));
    if (tid == 0) {
        #pragma unroll
        for (int s = 0; s < NS; s++) {
            asm volatile("mbarrier.init.shared.b64 [%0], 1;" :: "r"(sb + 8  + s * 8) : "memory");
            asm volatile("mbarrier.init.shared.b64 [%0], 1;" :: "r"(sb + 32 + s * 8) : "memory");
        }
        asm volatile("mbarrier.init.shared.b64 [%0], 1;" :: "r"(sb + 56) : "memory");
    }
    __syncthreads();

    const int rowA = off + m0;

    if (tid == 96) {
        // ================= producer: TMA =================
        for (int kc = 0; kc < NCHUNK; kc++) {
            const int s = kc % NS;
            const int r = kc / NS;
            WAIT_PARITY(sb + 32 + s * 8, (r & 1) ^ 1);   // stage free (first pass immediate)
            uint32_t full = sb + 8 + s * 8;
            asm volatile("mbarrier.arrive.expect_tx.shared.b64 _, [%0], %1;"
                         :: "r"(full), "r"(STAGE_BYTES) : "memory");
            uint32_t st = sb + 1024 + (uint32_t)s * STAGE_BYTES;
            int kx = kc * 64;
            TMA3D(st + 0,     &tmA, kx, rowA, 0, full);
            TMA3D(st + OFF_B, &tmB, kx, bn,   e, full);
        }
    } else if (tid == 0) {
        // ================= consumer: MMA =================
        for (int kc = 0; kc < NCHUNK; kc++) {
            const int s = kc % NS;
            const int r = kc / NS;
            WAIT_PARITY(sb + 8 + s * 8, r & 1);          // data ready
            uint32_t st = sb + 1024 + (uint32_t)s * STAGE_BYTES;
            uint64_t dA = mkdesc(st), dB = mkdesc(st + OFF_B);
            #pragma unroll
            for (int ks = 0; ks < 4; ks++) {
                uint64_t oa = (uint64_t)(ks * 2);
                mma_ss<NT>(tmem, dA + oa, dB + oa, !(kc == 0 && ks == 0));
            }
            asm volatile(
                "tcgen05.commit.cta_group::1.mbarrier::arrive::one.shared::cluster.b64 [%0];"
                :: "r"(sb + 32 + s * 8) : "memory");
        }
        asm volatile(
            "tcgen05.commit.cta_group::1.mbarrier::arrive::one.shared::cluster.b64 [%0];"
            :: "r"(sb + 56) : "memory");
    }

    WAIT_PARITY(sb + 56, 0);
    asm volatile("tcgen05.fence::after_thread_sync;" ::: "memory");

    // ---- epilogue: thread tid owns output row tid of the tile ----
    const float* bb = bias + (size_t)e * N;
    const bool valid = (m0 + tid) < cnt;
    const int srow = off + m0 + tid;
    #pragma unroll
    for (int cb = 0; cb < NT / 32; cb++) {
        uint32_t d[32];
        LDTM_X32(d, tmem + cb * 32);
        asm volatile("tcgen05.wait::ld.sync.aligned;" ::: "memory");
        if (valid) {
            int n0 = bn + cb * 32;
            if (PHASE == 1) {
                #pragma unroll
                for (int c = 0; c < 32; c += 8) {
                    __half h[8];
                    #pragma unroll
                    for (int j = 0; j < 8; j++)
                        h[j] = __float2half_rn(
                            fmaxf(__uint_as_float(d[c + j]) + __ldg(bb + n0 + c + j), 0.f));
                    *(uint4*)(g_h + (size_t)srow * DH + n0 + c) =
                        make_uint4(pack2(h[0], h[1]), pack2(h[2], h[3]),
                                   pack2(h[4], h[5]), pack2(h[6], h[7]));
                }
            } else {
                int otok = g_idx[srow];
                #pragma unroll
                for (int c = 0; c < 32; c += 4) {
                    float4 v;
                    v.x = __uint_as_float(d[c])   + __ldg(bb + n0 + c);
                    v.y = __uint_as_float(d[c+1]) + __ldg(bb + n0 + c + 1);
                    v.z = __uint_as_float(d[c+2]) + __ldg(bb + n0 + c + 2);
                    v.w = __uint_as_float(d[c+3]) + __ldg(bb + n0 + c + 3);
                    *(float4*)(OUT + (size_t)otok * DOUT + n0 + c) = v;
                }
            }
        }
    }
    asm volatile("tcgen05.fence::before_thread_sync;" ::: "memory");
    __syncthreads();
    if (tid == 0) {
        #pragma unroll
        for (int s = 0; s < NS; s++) {
            asm volatile("mbarrier.inval.shared.b64 [%0];" :: "r"(sb + 8  + s * 8) : "memory");
            asm volatile("mbarrier.inval.shared.b64 [%0];" :: "r"(sb + 32 + s * 8) : "memory");
        }
        asm volatile("mbarrier.inval.shared.b64 [%0];" :: "r"(sb + 56) : "memory");
    }
    __syncthreads();
    if (wid == 0)
        asm volatile("tcgen05.dealloc.cta_group::1.sync.aligned.b32 %0, %1;"
                     :: "r"(tmem), "r"((uint32_t)NT));
#endif // TC_OK
}

// ================= host: tensormap builder =================
typedef CUresult (*PFN_tmEncode)(CUtensorMap*, CUtensorMapDataType, cuuint32_t, void*,
                                 const cuuint64_t*, const cuuint64_t*, const cuuint32_t*,
                                 const cuuint32_t*, CUtensorMapInterleave, CUtensorMapSwizzle,
                                 CUtensorMapL2promotion, CUtensorMapFloatOOBfill);

static void make_map(PFN_tmEncode enc, CUtensorMap* tm, void* ptr,
                     uint64_t d0, uint64_t d1, uint64_t d2, uint32_t box1) {
    cuuint64_t dims[3]    = {d0, d1, d2};
    cuuint64_t strides[2] = {d0 * 2, d0 * d1 * 2};
    cuuint32_t box[3]     = {64, box1, 1};
    cuuint32_t es[3]      = {1, 1, 1};
    enc(tm, CU_TENSOR_MAP_DATA_TYPE_FLOAT16, 3, ptr, dims, strides, box, es,
        CU_TENSOR_MAP_INTERLEAVE_NONE, CU_TENSOR_MAP_SWIZZLE_128B,
        CU_TENSOR_MAP_L2_PROMOTION_L2_128B, CU_TENSOR_MAP_FLOAT_OOB_FILL_NONE);
}

extern "C" void kernel_launch(void* const* d_in, const int* in_sizes, int n_in,
                              void* d_out, int out_size) {
    const float* x      = (const float*)d_in[0];
    const int*   groups = (const int*)d_in[1];   // int32 (JAX demotes int64)
    const float* W1     = (const float*)d_in[2];
    const float* b1     = (const float*)d_in[3];
    const float* W2     = (const float*)d_in[4];
    const float* b2     = (const float*)d_in[5];
    float* out = (float*)d_out;

    // gemm1: NS=2 x 48KB; gemm2: NS=3 x 32KB -> both 99328 B, 2 CTAs/SM
    constexpr int SMEM_BYTES = 1024 + 2 * (128 * 128 + 256 * 128);

    static bool init_done = false;
    static cudaStream_t s_w1, s_w2;
    static cudaEvent_t evF, ev1, ev2;
    if (!init_done) {
        cudaFuncSetAttribute(gemm_tc<1, 256, 2>, cudaFuncAttributeMaxDynamicSharedMemorySize, SMEM_BYTES);
        cudaFuncSetAttribute(gemm_tc<2, 128, 3>, cudaFuncAttributeMaxDynamicSharedMemorySize, SMEM_BYTES);
        cudaStreamCreateWithFlags(&s_w1, cudaStreamNonBlocking);
        cudaStreamCreateWithFlags(&s_w2, cudaStreamNonBlocking);
        cudaEventCreateWithFlags(&evF, cudaEventDisableTiming);
        cudaEventCreateWithFlags(&ev1, cudaEventDisableTiming);
        cudaEventCreateWithFlags(&ev2, cudaEventDisableTiming);
        init_done = true;
    }

    PFN_tmEncode enc = nullptr;
    cudaDriverEntryPointQueryResult qres;
    cudaGetDriverEntryPoint("cuTensorMapEncodeTiled", (void**)&enc,
                            cudaEnableDefault, &qres);

    __half *xp, *hp, *w1p, *w2p;
    cudaGetSymbolAddress((void**)&xp,  g_x);
    cudaGetSymbolAddress((void**)&hp,  g_h);
    cudaGetSymbolAddress((void**)&w1p, g_w1);
    cudaGetSymbolAddress((void**)&w2p, g_w2);

    CUtensorMap tA1, tB1, tA2, tB2;
    make_map(enc, &tA1, xp,  DIN, NTOK, 1,  128);
    make_map(enc, &tB1, w1p, DIN, DH,   NE, 256);
    make_map(enc, &tA2, hp,  DH,  NTOK, 1,  128);
    make_map(enc, &tB2, w2p, DH,  DOUT, NE, 128);

    // fork: W conversions depend only on W inputs
    cudaEventRecord(evF, 0);
    cudaStreamWaitEvent(s_w1, evF, 0);
    cudaStreamWaitEvent(s_w2, evF, 0);
    k_convert_w<<<dim3(DH / 32, DIN / 32, NE), dim3(32, 8), 0, s_w1>>>(W1, w1p, DIN, DH);
    k_convert_w<<<dim3(DOUT / 32, DH / 32, NE), dim3(32, 8), 0, s_w2>>>(W2, w2p, DH, DOUT);
    cudaEventRecord(ev1, s_w1);
    cudaEventRecord(ev2, s_w2);

    // main stream: routing + x conversion (independent of W)
    k_route<<<1, 1024>>>(groups);
    k_convert_x<<<(NTOK * DIN / 4) / 256, 256>>>(x);

    // join w1 -> gemm1; join w2 -> gemm2
    cudaStreamWaitEvent(0, ev1, 0);
    gemm_tc<1, 256, 2><<<dim3(DH / 256,  NE * TPE), 128, SMEM_BYTES>>>(tA1, tB1, b1, nullptr);
    cudaStreamWaitEvent(0, ev2, 0);
    gemm_tc<2, 128, 3><<<dim3(DOUT / 128, NE * TPE), 128, SMEM_BYTES>>>(tA2, tB2, b2, out);
}

// round 14
// speedup vs baseline: 1.2181x; 1.2181x over previous
#include <cuda_runtime.h>
#include <cuda_fp16.h>
#include <cuda.h>
#include <cstdint>

#define NTOK 8192
#define DIN  512
#define DH   2048
#define DOUT 512
#define NE   8
#define TPE  64   // max m-tiles (128 rows) per expert
#define NS   2    // pipeline stages
#define NT   256  // n-tile

#if defined(__CUDA_ARCH__) && (__CUDA_ARCH__ >= 1000) && \
    (defined(__CUDA_ARCH_FEAT_SM103_ALL) || defined(__CUDA_ARCH_FEAT_SM100_ALL))
#define TC_OK 1
#else
#define TC_OK 0
#endif

// ---- scratch (__device__ globals: allocation-free rule) ----
__device__ int g_cnt[NE], g_off[NE], g_idx[NTOK];
__device__ __half g_x[(size_t)NTOK * DIN];               // sorted x (fp16)
__device__ __half g_h[(size_t)NTOK * DH];                // sorted h (fp16)
__device__ __half g_w1[(size_t)NE * DH * DIN];           // [e][n][k] fp16
__device__ __half g_w2[(size_t)NE * DOUT * DH];          // [e][n][k] fp16

// ================= helpers =================
__device__ __forceinline__ uint32_t smem_u32(const void* p) {
    uint32_t a;
    asm("{ .reg .u64 t; cvta.to.shared.u64 t, %1; cvt.u32.u64 %0, t; }" : "=r"(a) : "l"(p));
    return a;
}

static constexpr uint64_t DESC_BASE =
    (uint64_t(2) << 61) | (uint64_t(1) << 46) | (uint64_t(64) << 32) | (uint64_t(1) << 16);
__device__ __forceinline__ uint64_t mkdesc(uint32_t addr) {
    return DESC_BASE | ((uint64_t)(addr >> 4) & 0x3FFF);
}

// kind::f16, f32 accum, M=128 (8<<24), N/8<<17
#define MMA_IDESC (0x08000010u | ((NT / 8) << 17))

__device__ __forceinline__ uint32_t pack2(__half a, __half b) {
    __half2 p = __halves2half2(a, b);
    return *reinterpret_cast<uint32_t*>(&p);
}

#if TC_OK
__device__ __forceinline__ void mma_ss(uint32_t d, uint64_t a, uint64_t b, bool acc) {
    uint32_t en = acc ? 1u : 0u;
    asm volatile(
        "{\n\t.reg .pred p;\n\tsetp.ne.u32 p, %4, 0;\n\t"
        "tcgen05.mma.cta_group::1.kind::f16 [%0], %1, %2, %3, {%5,%5,%5,%5}, p;\n\t}"
        :: "r"(d), "l"(a), "l"(b), "r"(MMA_IDESC), "r"(en), "r"(0u) : "memory");
}

#define WAIT_PARITY(mbar, ph) do {                                              \
    uint32_t _m = (mbar), _p = (ph), _d;                                        \
    asm volatile("{\n\t.reg .pred p;\n\t"                                       \
        "mbarrier.try_wait.parity.acquire.cta.shared::cta.b64 p, [%1], %2;\n\t" \
        "selp.b32 %0,1,0,p;\n\t}" : "=r"(_d) : "r"(_m), "r"(_p) : "memory");    \
    if (!_d) {                                                                  \
        asm volatile("{\n\t.reg .pred P1;\n\t"                                  \
            "WL_%=:\n\t"                                                        \
            "mbarrier.try_wait.parity.acquire.cta.shared::cta.b64 P1, [%0], %1, 0x989680;\n\t" \
            "@P1 bra.uni WD_%=;\n\tbra.uni WL_%=;\n\tWD_%=:\n\t}"               \
            :: "r"(_m), "r"(_p) : "memory");                                    \
    }                                                                           \
} while (0)

#define TMA3D(smaddr, tmap, cx, cy, cz, mbar)                                      \
    asm volatile(                                                                  \
        "cp.async.bulk.tensor.3d.shared::cta.global.tile.mbarrier::complete_tx::bytes " \
        "[%0], [%1, {%2, %3, %4}], [%5];"                                          \
        :: "r"(smaddr), "l"(tmap), "r"(cx), "r"(cy), "r"(cz), "r"(mbar) : "memory")

#define LDTM_X32(r, ta)                                                          \
    asm volatile("tcgen05.ld.sync.aligned.32x32b.x32.b32 "                       \
        "{%0,%1,%2,%3,%4,%5,%6,%7,%8,%9,%10,%11,%12,%13,%14,%15,"                \
        "%16,%17,%18,%19,%20,%21,%22,%23,%24,%25,%26,%27,%28,%29,%30,%31}, [%32];" \
        : "=r"((r)[0]),"=r"((r)[1]),"=r"((r)[2]),"=r"((r)[3]),                   \
          "=r"((r)[4]),"=r"((r)[5]),"=r"((r)[6]),"=r"((r)[7]),                   \
          "=r"((r)[8]),"=r"((r)[9]),"=r"((r)[10]),"=r"((r)[11]),                 \
          "=r"((r)[12]),"=r"((r)[13]),"=r"((r)[14]),"=r"((r)[15]),               \
          "=r"((r)[16]),"=r"((r)[17]),"=r"((r)[18]),"=r"((r)[19]),               \
          "=r"((r)[20]),"=r"((r)[21]),"=r"((r)[22]),"=r"((r)[23]),               \
          "=r"((r)[24]),"=r"((r)[25]),"=r"((r)[26]),"=r"((r)[27]),               \
          "=r"((r)[28]),"=r"((r)[29]),"=r"((r)[30]),"=r"((r)[31])                \
        : "r"(ta))
#endif // TC_OK

// ================= routing: ONE kernel (single block) =================
__global__ void __launch_bounds__(1024) k_route(const int* __restrict__ g) {
    __shared__ int c[NE], pos[NE];
    int tid = threadIdx.x;
    if (tid < NE) { c[tid] = 0; }
    __syncthreads();
    #pragma unroll
    for (int i = tid; i < NTOK; i += 1024) atomicAdd(&c[g[i] & (NE - 1)], 1);
    __syncthreads();
    if (tid == 0) {
        int s = 0;
        for (int e = 0; e < NE; e++) { g_off[e] = s; g_cnt[e] = c[e]; pos[e] = s; s += c[e]; }
    }
    __syncthreads();
    #pragma unroll
    for (int i = tid; i < NTOK; i += 1024) {
        int e = g[i] & (NE - 1);
        int p = atomicAdd(&pos[e], 1);
        g_idx[p] = i;
    }
}

// ================= pre-conversion =================
// x gather+convert: each thread converts 8 floats -> one 16B store
__global__ void __launch_bounds__(256) k_convert_x(const float* __restrict__ x) {
    int i = blockIdx.x * blockDim.x + threadIdx.x;   // 0 .. NTOK*DIN/8-1
    int row = i >> 6;                 // DIN/8 = 64 chunks per row
    int c = (i & 63) * 8;
    int tok = g_idx[row];
    const float4* src = (const float4*)(x + (size_t)tok * DIN + c);
    float4 v0 = src[0], v1 = src[1];
    *(uint4*)(g_x + (size_t)row * DIN + c) = make_uint4(
        pack2(__float2half_rn(v0.x), __float2half_rn(v0.y)),
        pack2(__float2half_rn(v0.z), __float2half_rn(v0.w)),
        pack2(__float2half_rn(v1.x), __float2half_rn(v1.y)),
        pack2(__float2half_rn(v1.z), __float2half_rn(v1.w)));
}

// W [e][K][N] fp32 -> Wt [e][N][K] fp16.
// Tile 128(K) x 32(N); writes are 16B uint4, rows land as 256B contiguous runs.
__global__ void __launch_bounds__(256) k_convert_w(const float* __restrict__ W,
                                                   __half* __restrict__ Wt,
                                                   int K, int N) {
    __shared__ float t[128][33];
    int e = blockIdx.z;
    int k0 = blockIdx.y * 128, n0 = blockIdx.x * 32;
    int tx = threadIdx.x & 31, ty = threadIdx.x >> 5;   // (32, 8)
    const float* Wb = W + (size_t)e * K * N;
    #pragma unroll
    for (int j = 0; j < 16; j++) {
        int kk = ty + j * 8;
        t[kk][tx] = Wb[(size_t)(k0 + kk) * N + n0 + tx];
    }
    __syncthreads();
    __half* Tb = Wt + ((size_t)e * N + n0) * K + k0;
    #pragma unroll
    for (int it = 0; it < 2; it++) {
        int idx = threadIdx.x + it * 256;   // 0..511
        int nn = idx >> 4;                  // output row (0..31)
        int kg = (idx & 15) * 8;            // k base (0..120)
        uint32_t p[4];
        #pragma unroll
        for (int j = 0; j < 4; j++)
            p[j] = pack2(__float2half_rn(t[kg + 2 * j][nn]),
                         __float2half_rn(t[kg + 2 * j + 1][nn]));
        *(uint4*)(Tb + (size_t)nn * K + kg) = make_uint4(p[0], p[1], p[2], p[3]);
    }
}

// ================= tcgen05 fp16 GEMM, TMA pipeline, 2 CTAs/SM =================
// PHASE 1: h = relu(x_s @ W1t^T + b1)  K=512,  N=2048
// PHASE 2: out = h_s @ W2t^T + b2      K=2048, N=512  (scatter store)
template<int PHASE>
__global__ void __launch_bounds__(128, 2)
gemm_tc(const __grid_constant__ CUtensorMap tmA,
        const __grid_constant__ CUtensorMap tmB,
        const float* __restrict__ bias, float* __restrict__ OUT)
{
#if TC_OK
    constexpr int K = (PHASE == 1) ? DIN : DH;
    constexpr int N = (PHASE == 1) ? DH : DOUT;
    constexpr int NCHUNK = K / 64;
    constexpr uint32_t A_BYTES = 128 * 128;                     // 16 KB
    constexpr uint32_t B_BYTES = NT * 128;                      // 32 KB
    constexpr uint32_t STAGE_BYTES = A_BYTES + B_BYTES;         // 48 KB
    constexpr uint32_t OFF_B = A_BYTES;

    const int e  = blockIdx.y / TPE;
    const int mt = blockIdx.y % TPE;
    const int cnt = g_cnt[e];
    const int m0  = mt * 128;
    if (m0 >= cnt) return;
    const int off = g_off[e];
    const int bn  = blockIdx.x * NT;

    extern __shared__ char smem[];
    const uint32_t sb = smem_u32(smem);
    // header: [0] tmem ptr; full mbars at 8+8s; empty at 32+8s; done at 56
    const int tid = threadIdx.x, wid = tid >> 5;

    if (wid == 0) {
        asm volatile("tcgen05.alloc.cta_group::1.sync.aligned.shared::cta.b32 [%0], %1;"
                     :: "r"(sb), "r"(256u) : "memory");
        asm volatile("tcgen05.relinquish_alloc_permit.cta_group::1.sync.aligned;");
    }
    __syncthreads();
    uint32_t tmem;
    asm volatile("ld.shared.b32 %0,[%1];" : "=r"(tmem) : "r"(sb));
    if (tid == 0) {
        #pragma unroll
        for (int s = 0; s < NS; s++) {
            asm volatile("mbarrier.init.shared.b64 [%0], 1;" :: "r"(sb + 8  + s * 8) : "memory");
            asm volatile("mbarrier.init.shared.b64 [%0], 1;" :: "r"(sb + 32 + s * 8) : "memory");
        }
        asm volatile("mbarrier.init.shared.b64 [%0], 1;" :: "r"(sb + 56) : "memory");
    }
    __syncthreads();

    const int rowA = off + m0;   // OOB rows -> TMA zero fill

    if (tid == 96) {
        // ================= producer: TMA =================
        for (int kc = 0; kc < NCHUNK; kc++) {
            const int s = kc % NS;
            const int r = kc / NS;
            WAIT_PARITY(sb + 32 + s * 8, (r & 1) ^ 1);   // stage free (first pass immediate)
            uint32_t full = sb + 8 + s * 8;
            asm volatile("mbarrier.arrive.expect_tx.shared.b64 _, [%0], %1;"
                         :: "r"(full), "r"(STAGE_BYTES) : "memory");
            uint32_t st = sb + 1024 + (uint32_t)s * STAGE_BYTES;
            int kx = kc * 64;
            TMA3D(st + 0,     &tmA, kx, rowA, 0, full);
            TMA3D(st + OFF_B, &tmB, kx, bn,   e, full);
        }
    } else if (tid == 0) {
        // ================= consumer: MMA =================
        for (int kc = 0; kc < NCHUNK; kc++) {
            const int s = kc % NS;
            const int r = kc / NS;
            WAIT_PARITY(sb + 8 + s * 8, r & 1);          // data ready
            uint32_t st = sb + 1024 + (uint32_t)s * STAGE_BYTES;
            uint64_t dA = mkdesc(st), dB = mkdesc(st + OFF_B);
            #pragma unroll
            for (int ks = 0; ks < 4; ks++) {
                uint64_t oa = (uint64_t)(ks * 2);
                mma_ss(tmem, dA + oa, dB + oa, !(kc == 0 && ks == 0));
            }
            asm volatile(
                "tcgen05.commit.cta_group::1.mbarrier::arrive::one.shared::cluster.b64 [%0];"
                :: "r"(sb + 32 + s * 8) : "memory");
        }
        asm volatile(
            "tcgen05.commit.cta_group::1.mbarrier::arrive::one.shared::cluster.b64 [%0];"
            :: "r"(sb + 56) : "memory");
    }

    // all threads wait for the final MMA
    WAIT_PARITY(sb + 56, 0);
    asm volatile("tcgen05.fence::after_thread_sync;" ::: "memory");

    // ---- epilogue: thread tid owns output row tid of the tile ----
    const float* bb = bias + (size_t)e * N;
    const bool valid = (m0 + tid) < cnt;
    const int srow = off + m0 + tid;
    #pragma unroll
    for (int cb = 0; cb < NT / 32; cb++) {
        uint32_t d[32];
        LDTM_X32(d, tmem + cb * 32);
        asm volatile("tcgen05.wait::ld.sync.aligned;" ::: "memory");
        if (valid) {
            int n0 = bn + cb * 32;
            if (PHASE == 1) {
                #pragma unroll
                for (int c = 0; c < 32; c += 8) {
                    __half h[8];
                    #pragma unroll
                    for (int j = 0; j < 8; j++)
                        h[j] = __float2half_rn(
                            fmaxf(__uint_as_float(d[c + j]) + __ldg(bb + n0 + c + j), 0.f));
                    *(uint4*)(g_h + (size_t)srow * DH + n0 + c) =
                        make_uint4(pack2(h[0], h[1]), pack2(h[2], h[3]),
                                   pack2(h[4], h[5]), pack2(h[6], h[7]));
                }
            } else {
                int otok = g_idx[srow];
                #pragma unroll
                for (int c = 0; c < 32; c += 4) {
                    float4 v;
                    v.x = __uint_as_float(d[c])   + __ldg(bb + n0 + c);
                    v.y = __uint_as_float(d[c+1]) + __ldg(bb + n0 + c + 1);
                    v.z = __uint_as_float(d[c+2]) + __ldg(bb + n0 + c + 2);
                    v.w = __uint_as_float(d[c+3]) + __ldg(bb + n0 + c + 3);
                    *(float4*)(OUT + (size_t)otok * DOUT + n0 + c) = v;
                }
            }
        }
    }
    asm volatile("tcgen05.fence::before_thread_sync;" ::: "memory");
    __syncthreads();
    if (tid == 0) {
        #pragma unroll
        for (int s = 0; s < NS; s++) {
            asm volatile("mbarrier.inval.shared.b64 [%0];" :: "r"(sb + 8  + s * 8) : "memory");
            asm volatile("mbarrier.inval.shared.b64 [%0];" :: "r"(sb + 32 + s * 8) : "memory");
        }
        asm volatile("mbarrier.inval.shared.b64 [%0];" :: "r"(sb + 56) : "memory");
    }
    __syncthreads();
    if (wid == 0)
        asm volatile("tcgen05.dealloc.cta_group::1.sync.aligned.b32 %0, %1;"
                     :: "r"(tmem), "r"(256u));
#endif // TC_OK
}

// ================= host: tensormap builder =================
typedef CUresult (*PFN_tmEncode)(CUtensorMap*, CUtensorMapDataType, cuuint32_t, void*,
                                 const cuuint64_t*, const cuuint64_t*, const cuuint32_t*,
                                 const cuuint32_t*, CUtensorMapInterleave, CUtensorMapSwizzle,
                                 CUtensorMapL2promotion, CUtensorMapFloatOOBfill);

static void make_map(PFN_tmEncode enc, CUtensorMap* tm, void* ptr,
                     uint64_t d0, uint64_t d1, uint64_t d2, uint32_t box1) {
    cuuint64_t dims[3]    = {d0, d1, d2};
    cuuint64_t strides[2] = {d0 * 2, d0 * d1 * 2};
    cuuint32_t box[3]     = {64, box1, 1};
    cuuint32_t es[3]      = {1, 1, 1};
    enc(tm, CU_TENSOR_MAP_DATA_TYPE_FLOAT16, 3, ptr, dims, strides, box, es,
        CU_TENSOR_MAP_INTERLEAVE_NONE, CU_TENSOR_MAP_SWIZZLE_128B,
        CU_TENSOR_MAP_L2_PROMOTION_L2_128B, CU_TENSOR_MAP_FLOAT_OOB_FILL_NONE);
}

extern "C" void kernel_launch(void* const* d_in, const int* in_sizes, int n_in,
                              void* d_out, int out_size) {
    const float* x      = (const float*)d_in[0];
    const int*   groups = (const int*)d_in[1];   // int32 (JAX demotes int64)
    const float* W1     = (const float*)d_in[2];
    const float* b1     = (const float*)d_in[3];
    const float* W2     = (const float*)d_in[4];
    const float* b2     = (const float*)d_in[5];
    float* out = (float*)d_out;

    constexpr int SMEM_BYTES = 1024 + NS * (128 * 128 + NT * 128);  // 99328 -> 2 CTAs/SM
    static bool attr_done = false;
    if (!attr_done) {
        cudaFuncSetAttribute(gemm_tc<1>, cudaFuncAttributeMaxDynamicSharedMemorySize, SMEM_BYTES);
        cudaFuncSetAttribute(gemm_tc<2>, cudaFuncAttributeMaxDynamicSharedMemorySize, SMEM_BYTES);
        attr_done = true;
    }

    PFN_tmEncode enc = nullptr;
    cudaDriverEntryPointQueryResult qres;
    cudaGetDriverEntryPoint("cuTensorMapEncodeTiled", (void**)&enc,
                            cudaEnableDefault, &qres);

    __half *xp, *hp, *w1p, *w2p;
    cudaGetSymbolAddress((void**)&xp,  g_x);
    cudaGetSymbolAddress((void**)&hp,  g_h);
    cudaGetSymbolAddress((void**)&w1p, g_w1);
    cudaGetSymbolAddress((void**)&w2p, g_w2);

    CUtensorMap tA1, tB1, tA2, tB2;
    make_map(enc, &tA1, xp,  DIN, NTOK, 1,  128);
    make_map(enc, &tB1, w1p, DIN, DH,   NE, NT);
    make_map(enc, &tA2, hp,  DH,  NTOK, 1,  128);
    make_map(enc, &tB2, w2p, DH,  DOUT, NE, NT);

    k_route<<<1, 1024>>>(groups);
    k_convert_x<<<(NTOK * DIN / 8) / 256, 256>>>(x);
    k_convert_w<<<dim3(DH / 32, DIN / 128, NE), 256>>>(W1, w1p, DIN, DH);
    k_convert_w<<<dim3(DOUT / 32, DH / 128, NE), 256>>>(W2, w2p, DH, DOUT);

    gemm_tc<1><<<dim3(DH / NT,   NE * TPE), 128, SMEM_BYTES>>>(tA1, tB1, b1, nullptr);
    gemm_tc<2><<<dim3(DOUT / NT, NE * TPE), 128, SMEM_BYTES>>>(tA2, tB2, b2, out);
}